// round 2
// baseline (speedup 1.0000x reference)
#include <cuda_runtime.h>
#include <math.h>
#include <stdint.h>

// Problem dims
#define Bz   256
#define Nn   196
#define Dd   1024
#define HID  1024
#define ATT  256
#define SIN  1024
#define WID  1024
#define ISD  256
#define Ss   10
#define G4   (4*HID)

// ---------------- device scratch (no runtime allocs allowed) ----------------
__device__ float g_vea[(size_t)Bz*Nn*ATT];   // vis_enc_att  [B,N,ATT]  ~51MB
__device__ float g_h[2][Bz*HID];
__device__ float g_c[Bz*HID];
__device__ float g_dec[Bz*ATT];
__device__ float g_logits[Bz*Nn];
__device__ float g_attout[Bz*Dd];
__device__ float g_ctx[Bz*SIN];
__device__ float g_gates[(size_t)Bz*G4];
__device__ float g_ppre[Bz*ISD];

// ---------------- helpers ----------------
__device__ __forceinline__ float tanha(float x) {
    float y;
    asm("tanh.approx.f32 %0, %1;" : "=f"(y) : "f"(x));
    return y;
}
__device__ __forceinline__ float sigmoidf_(float x) {
    return 1.0f / (1.0f + expf(-x));
}

// ---------------- generic dual-source GEMM ----------------
// C[m, n] = act( sum_k A1[m,k]*W1[n,k] (+ sum_k A2[m,k]*W2[n,k]) + b1[n] (+ b2[n]) )
// A row-major [M,K], W row-major [N,K] (PyTorch Linear layout), C row-major ld=ldC.
// ACT: 0 = none, 1 = tanh (accurate)
template<int BM, int BN, int BK, int TM, int TN, int ACT>
__global__ void __launch_bounds__(256)
gemm_dual(const float* __restrict__ A1, const float* __restrict__ W1, int K1,
          const float* __restrict__ A2, const float* __restrict__ W2, int K2,
          const float* __restrict__ b1, const float* __restrict__ b2,
          float* __restrict__ C, int ldC)
{
    __shared__ float As[BK][BM + 1];
    __shared__ float Ws[BK][BN + 1];
    constexpr int NT = (BM / TM) * (BN / TN);   // must be 256
    const int tx = threadIdx.x;
    const int m0 = blockIdx.y * BM;
    const int n0 = blockIdx.x * BN;
    const int tm = (tx / (BN / TN)) * TM;
    const int tn = (tx % (BN / TN)) * TN;

    float acc[TM][TN];
    #pragma unroll
    for (int i = 0; i < TM; i++)
        #pragma unroll
        for (int j = 0; j < TN; j++) acc[i][j] = 0.f;

    #pragma unroll 1
    for (int src = 0; src < 2; ++src) {
        const float* A = src ? A2 : A1;
        const float* W = src ? W2 : W1;
        const int K = src ? K2 : K1;
        if (A == nullptr) break;
        #pragma unroll 1
        for (int k0 = 0; k0 < K; k0 += BK) {
            // load A tile (BM x BK) transposed into As[k][m]
            constexpr int AV = (BM * BK / 4) / NT;   // float4 loads per thread
            #pragma unroll
            for (int t = 0; t < AV; t++) {
                int i = tx + t * NT;
                int row = i / (BK / 4);
                int kc  = (i % (BK / 4)) * 4;
                float4 v = *reinterpret_cast<const float4*>(A + (size_t)(m0 + row) * K + k0 + kc);
                As[kc + 0][row] = v.x; As[kc + 1][row] = v.y;
                As[kc + 2][row] = v.z; As[kc + 3][row] = v.w;
            }
            constexpr int WV = (BN * BK / 4) / NT;
            #pragma unroll
            for (int t = 0; t < WV; t++) {
                int i = tx + t * NT;
                int row = i / (BK / 4);
                int kc  = (i % (BK / 4)) * 4;
                float4 v = *reinterpret_cast<const float4*>(W + (size_t)(n0 + row) * K + k0 + kc);
                Ws[kc + 0][row] = v.x; Ws[kc + 1][row] = v.y;
                Ws[kc + 2][row] = v.z; Ws[kc + 3][row] = v.w;
            }
            __syncthreads();
            #pragma unroll
            for (int kk = 0; kk < BK; ++kk) {
                float ar[TM], wr[TN];
                #pragma unroll
                for (int i = 0; i < TM; i++) ar[i] = As[kk][tm + i];
                #pragma unroll
                for (int j = 0; j < TN; j++) wr[j] = Ws[kk][tn + j];
                #pragma unroll
                for (int i = 0; i < TM; i++)
                    #pragma unroll
                    for (int j = 0; j < TN; j++)
                        acc[i][j] = fmaf(ar[i], wr[j], acc[i][j]);
            }
            __syncthreads();
        }
    }

    #pragma unroll
    for (int i = 0; i < TM; i++) {
        #pragma unroll
        for (int j = 0; j < TN; j++) {
            int n = n0 + tn + j;
            float v = acc[i][j];
            if (b1) v += b1[n];
            if (b2) v += b2[n];
            if (ACT == 1) v = tanhf(v);
            C[(size_t)(m0 + tm + i) * ldC + n] = v;
        }
    }
}

// ---------------- attention: logits[b,n] = sum_a tanh(vea+dec)*w + fb ----------------
__global__ void __launch_bounds__(256)
att_logits_kernel(const float* __restrict__ vea, const float* __restrict__ dec,
                  const float* __restrict__ faw, const float* __restrict__ fab,
                  float* __restrict__ logits)
{
    const int b = blockIdx.x;
    __shared__ float sdec[ATT];
    __shared__ float sw[ATT];
    const int tx = threadIdx.x;
    sdec[tx] = dec[b * ATT + tx];
    sw[tx]   = faw[tx];
    __syncthreads();
    const int warp = tx >> 5, lane = tx & 31;
    const float bias = fab[0];
    for (int n = warp; n < Nn; n += 8) {
        const float* row = vea + ((size_t)b * Nn + n) * ATT;
        float s = 0.f;
        #pragma unroll
        for (int a0 = 0; a0 < ATT; a0 += 32) {
            int a = a0 + lane;
            s += tanha(row[a] + sdec[a]) * sw[a];
        }
        #pragma unroll
        for (int o = 16; o; o >>= 1) s += __shfl_xor_sync(0xffffffffu, s, o);
        if (lane == 0) logits[b * Nn + n] = s + bias;
    }
}

// ---------------- softmax over N + att_out = scores @ vis_enc ----------------
__global__ void __launch_bounds__(256)
softmax_attout_kernel(const float* __restrict__ logits, const float* __restrict__ vis,
                      float* __restrict__ attout)
{
    const int b = blockIdx.x;
    const int tx = threadIdx.x;
    __shared__ float sc[Nn];
    __shared__ float red[256];

    float v = (tx < Nn) ? logits[b * Nn + tx] : -INFINITY;
    red[tx] = v;
    __syncthreads();
    #pragma unroll
    for (int o = 128; o; o >>= 1) {
        if (tx < o) red[tx] = fmaxf(red[tx], red[tx + o]);
        __syncthreads();
    }
    float mx = red[0];
    __syncthreads();
    float e = (tx < Nn) ? expf(v - mx) : 0.f;
    red[tx] = e;
    __syncthreads();
    #pragma unroll
    for (int o = 128; o; o >>= 1) {
        if (tx < o) red[tx] += red[tx + o];
        __syncthreads();
    }
    float inv = 1.f / red[0];
    if (tx < Nn) sc[tx] = e * inv;
    __syncthreads();

    const float* base = vis + (size_t)b * Nn * Dd;
    const int d0 = tx * 4;
    float4 acc = make_float4(0.f, 0.f, 0.f, 0.f);
    #pragma unroll 4
    for (int n = 0; n < Nn; n++) {
        float s = sc[n];
        float4 x = *reinterpret_cast<const float4*>(base + (size_t)n * Dd + d0);
        acc.x = fmaf(s, x.x, acc.x);
        acc.y = fmaf(s, x.y, acc.y);
        acc.z = fmaf(s, x.z, acc.z);
        acc.w = fmaf(s, x.w, acc.w);
    }
    *reinterpret_cast<float4*>(attout + (size_t)b * Dd + d0) = acc;
}

// ---------------- LSTM elementwise ----------------
__global__ void __launch_bounds__(256)
lstm_kernel(const float* __restrict__ gates, float* __restrict__ c, float* __restrict__ hnew)
{
    const int idx = blockIdx.x * 256 + threadIdx.x;   // < B*HID
    const int b = idx / HID, hh = idx % HID;
    const float* gb = gates + (size_t)b * G4;
    float gi = gb[hh];
    float gf = gb[HID + hh];
    float gg = gb[2 * HID + hh];
    float go = gb[3 * HID + hh];
    float cn = sigmoidf_(gf) * c[idx] + sigmoidf_(gi) * tanhf(gg);
    c[idx] = cn;
    hnew[idx] = sigmoidf_(go) * tanhf(cn);
}

// ---------------- final stop head: p = ppre @ fw^T + fb ----------------
__global__ void __launch_bounds__(256)
stop_final_kernel(const float* __restrict__ ppre, const float* __restrict__ fw,
                  const float* __restrict__ fb, float* __restrict__ outp, int s)
{
    const int b = blockIdx.x;
    const int tx = threadIdx.x;   // 256 == ISD
    __shared__ float r0[256];
    __shared__ float r1[256];
    float v = ppre[b * ISD + tx];
    r0[tx] = v * fw[tx];
    r1[tx] = v * fw[ISD + tx];
    __syncthreads();
    #pragma unroll
    for (int o = 128; o; o >>= 1) {
        if (tx < o) { r0[tx] += r0[tx + o]; r1[tx] += r1[tx + o]; }
        __syncthreads();
    }
    if (tx == 0) {
        outp[(size_t)b * Ss * 2 + s * 2 + 0] = r0[0] + fb[0];
        outp[(size_t)b * Ss * 2 + s * 2 + 1] = r1[0] + fb[1];
    }
}

// ---------------- zero init h0, c ----------------
__global__ void zero2_kernel(float* __restrict__ a, float* __restrict__ b, int n)
{
    int i = blockIdx.x * 256 + threadIdx.x;
    if (i < n) { a[i] = 0.f; b[i] = 0.f; }
}

// ---------------- launch ----------------
extern "C" void kernel_launch(void* const* d_in, const int* in_sizes, int n_in,
                              void* d_out, int out_size)
{
    const float* vis        = (const float*)d_in[0];
    // d_in[1] = sentences (int64) — unused by the reference computation
    const float* enc_att_w  = (const float*)d_in[2];
    const float* enc_att_b  = (const float*)d_in[3];
    const float* dec_att_w  = (const float*)d_in[4];
    const float* dec_att_b  = (const float*)d_in[5];
    const float* full_att_w = (const float*)d_in[6];
    const float* full_att_b = (const float*)d_in[7];
    const float* ctx_w      = (const float*)d_in[8];
    const float* ctx_b      = (const float*)d_in[9];
    const float* W_ih       = (const float*)d_in[10];
    const float* b_ih       = (const float*)d_in[11];
    const float* W_hh       = (const float*)d_in[12];
    const float* b_hh       = (const float*)d_in[13];
    const float* topic_hid_w = (const float*)d_in[14];
    const float* topic_hid_b = (const float*)d_in[15];
    const float* topic_ctx_w = (const float*)d_in[16];
    const float* topic_ctx_b = (const float*)d_in[17];
    const float* stop_prev_w = (const float*)d_in[18];
    const float* stop_prev_b = (const float*)d_in[19];
    const float* stop_cur_w  = (const float*)d_in[20];
    const float* stop_cur_b  = (const float*)d_in[21];
    const float* final_stop_w = (const float*)d_in[22];
    const float* final_stop_b = (const float*)d_in[23];

    float* out = (float*)d_out;
    float* out_topics = out;                               // [B, S, WID]
    float* out_ps     = out + (size_t)Bz * Ss * WID;       // [B, S, 2]

    float *vea, *hbase, *c, *dec, *logits, *attout, *ctx, *gates, *ppre;
    cudaGetSymbolAddress((void**)&vea,    g_vea);
    cudaGetSymbolAddress((void**)&hbase,  g_h);
    cudaGetSymbolAddress((void**)&c,      g_c);
    cudaGetSymbolAddress((void**)&dec,    g_dec);
    cudaGetSymbolAddress((void**)&logits, g_logits);
    cudaGetSymbolAddress((void**)&attout, g_attout);
    cudaGetSymbolAddress((void**)&ctx,    g_ctx);
    cudaGetSymbolAddress((void**)&gates,  g_gates);
    cudaGetSymbolAddress((void**)&ppre,   g_ppre);
    float* h0 = hbase;
    float* h1 = hbase + Bz * HID;

    // zero h0 and c (deterministic per call)
    zero2_kernel<<<(Bz * HID + 255) / 256, 256>>>(h0, c, Bz * HID);

    // precompute vis_enc_att = vis_enc @ enc_att_w^T + b : [B*N, ATT]
    {
        dim3 grid(ATT / 64, (Bz * Nn) / 64);
        gemm_dual<64, 64, 32, 4, 4, 0><<<grid, 256>>>(
            vis, enc_att_w, Dd, nullptr, nullptr, 0,
            enc_att_b, nullptr, vea, ATT);
    }

    for (int s = 0; s < Ss; s++) {
        float* hc = (s & 1) ? h1 : h0;   // h (previous)
        float* hn = (s & 1) ? h0 : h1;   // h_new

        // dec = h @ dec_att_w^T + b : [B, ATT]
        gemm_dual<32, 32, 32, 2, 2, 0><<<dim3(ATT / 32, Bz / 32), 256>>>(
            hc, dec_att_w, HID, nullptr, nullptr, 0,
            dec_att_b, nullptr, dec, ATT);

        // logits
        att_logits_kernel<<<Bz, 256>>>(vea, dec, full_att_w, full_att_b, logits);

        // softmax + att_out
        softmax_attout_kernel<<<Bz, 256>>>(logits, vis, attout);

        // ctx = att_out @ ctx_w^T + b : [B, SIN]
        gemm_dual<64, 64, 32, 4, 4, 0><<<dim3(SIN / 64, Bz / 64), 256>>>(
            attout, ctx_w, Dd, nullptr, nullptr, 0,
            ctx_b, nullptr, ctx, SIN);

        // gates = ctx @ W_ih^T + b_ih + h @ W_hh^T + b_hh : [B, 4H]
        gemm_dual<64, 64, 32, 4, 4, 0><<<dim3(G4 / 64, Bz / 64), 256>>>(
            ctx, W_ih, SIN, hc, W_hh, HID,
            b_ih, b_hh, gates, G4);

        // LSTM elementwise -> c (in place), hn
        lstm_kernel<<<(Bz * HID) / 256, 256>>>(gates, c, hn);

        // topic = tanh(hn @ topic_hid^T + ctx @ topic_ctx^T + b1 + b2) -> out strided
        gemm_dual<64, 64, 32, 4, 4, 1><<<dim3(WID / 64, Bz / 64), 256>>>(
            hn, topic_hid_w, HID, ctx, topic_ctx_w, SIN,
            topic_hid_b, topic_ctx_b, out_topics + (size_t)s * WID, Ss * WID);

        // ppre = tanh(h_prev @ stop_prev^T + hn @ stop_cur^T + b1 + b2) : [B, ISD]
        gemm_dual<32, 32, 32, 2, 2, 1><<<dim3(ISD / 32, Bz / 32), 256>>>(
            hc, stop_prev_w, HID, hn, stop_cur_w, HID,
            stop_prev_b, stop_cur_b, ppre, ISD);

        // p = ppre @ final_stop_w^T + b -> out
        stop_final_kernel<<<Bz, 256>>>(ppre, final_stop_w, final_stop_b, out_ps, s);
    }
}

// round 4
// speedup vs baseline: 2.2608x; 2.2608x over previous
#include <cuda_runtime.h>
#include <cuda_bf16.h>
#include <math.h>
#include <stdint.h>

#define Bz   256
#define Nn   196
#define Dd   1024
#define HID  1024
#define ATT  256
#define SIN  1024
#define WID  1024
#define ISD  256
#define Ss   10
#define G4   (4*HID)

// ---------------- device scratch ----------------
__device__ float g_vea[(size_t)Bz*Nn*ATT];
__device__ float g_h[2][Bz*HID];
__device__ float g_c[Bz*HID];
__device__ float g_dec[Bz*ATT];
__device__ float g_logits[Bz*Nn];
__device__ float g_attout[Bz*Dd];
__device__ float g_ctx[Bz*SIN];
__device__ float g_gates[(size_t)Bz*G4];
__device__ float g_ppre[Bz*ISD];

#define WTOT 12582912
__device__ __nv_bfloat16 g_wh[WTOT];
__device__ __nv_bfloat16 g_wl[WTOT];
#define OFF_ENC  0
#define OFF_DEC  262144
#define OFF_CTX  524288
#define OFF_WIH  1572864
#define OFF_WHH  5767168
#define OFF_TH   9961472
#define OFF_TC   11010048
#define OFF_SP   12058624
#define OFF_SC   12320768

// ---------------- helpers ----------------
__device__ __forceinline__ uint32_t s2u(const void* p) {
    uint32_t r;
    asm("{ .reg .u64 t; cvta.to.shared.u64 t, %1; cvt.u32.u64 %0, t; }" : "=r"(r) : "l"(p));
    return r;
}
__device__ __forceinline__ float tanha(float x) {
    float y; asm("tanh.approx.f32 %0, %1;" : "=f"(y) : "f"(x)); return y;
}
__device__ __forceinline__ float sigmoidf_(float x) { return 1.0f / (1.0f + expf(-x)); }

#define SMEM_SWZ(o) ((o) ^ (((o) >> 3) & 0x70))

__device__ __forceinline__ void cpa16(uint32_t dst, const void* src) {
    asm volatile("cp.async.cg.shared.global [%0], [%1], 16;" :: "r"(dst), "l"(src));
}
#define LDSM4(r, addr) \
    asm volatile("ldmatrix.sync.aligned.m8n8.x4.shared.b16 {%0,%1,%2,%3}, [%4];" \
        : "=r"((r)[0]), "=r"((r)[1]), "=r"((r)[2]), "=r"((r)[3]) : "r"(addr))
#define MMA16816(d, a, b0, b1) \
    asm volatile("mma.sync.aligned.m16n8k16.row.col.f32.bf16.bf16.f32 " \
        "{%0,%1,%2,%3}, {%4,%5,%6,%7}, {%8,%9}, {%0,%1,%2,%3};" \
        : "+f"((d)[0]), "+f"((d)[1]), "+f"((d)[2]), "+f"((d)[3]) \
        : "r"((a)[0]), "r"((a)[1]), "r"((a)[2]), "r"((a)[3]), "r"(b0), "r"(b1))

// ============================================================================
// mma.sync bf16 GEMM with 3-term hi/lo fp32 emulation.
// C[M,N] = act( sum_seg A_seg @ W_seg^T + b1 (+ b2) )
// A fp32 [M,K] (split on the fly); W pre-split bf16 hi/lo [N,K] row-major.
// Block tile BM x 64, K-chunk 64, cp.async double-buffered W, reg-staged A.
// ============================================================================
template<int BM, int ACT>
__global__ void __launch_bounds__(BM == 128 ? 256 : 128, 1)
gemm_ms(const float* __restrict__ A0, const __nv_bfloat16* __restrict__ W0h,
        const __nv_bfloat16* __restrict__ W0l, int K0,
        const float* __restrict__ A1, const __nv_bfloat16* __restrict__ W1h,
        const __nv_bfloat16* __restrict__ W1l, int K1,
        const float* __restrict__ b1, const float* __restrict__ b2,
        float* __restrict__ C, int ldC)
{
    constexpr int T = (BM == 128) ? 256 : 128;
    constexpr int STAGE = 2 * BM * 128 + 2 * 64 * 128;   // Ahi,Alo,Whi,Wlo
    extern __shared__ char dsm[];
    const int tid = threadIdx.x;
    const int wid = tid >> 5, lane = tid & 31;
    const int warp_m = wid >> 1, warp_n = wid & 1;
    const int m0 = blockIdx.y * BM;
    const int n0 = blockIdx.x * 64;

    const uint32_t sbase = s2u(dsm);

    // lane constants for ldmatrix addressing
    const int lt = lane >> 3;
    const int m_in = (lt & 1) * 8 + (lane & 7);
    const int kb_a = (lt >> 1) * 16;
    const int n_in = (lt >> 1) * 8 + (lane & 7);
    const int kb_b = (lt & 1) * 16;

    const int nk0 = K0 >> 6;
    const int nk1 = A1 ? (K1 >> 6) : 0;
    const int nItems = nk0 + nk1;

    float acc[2][4][4];
    #pragma unroll
    for (int f = 0; f < 2; f++)
        #pragma unroll
        for (int nf = 0; nf < 4; nf++)
            #pragma unroll
            for (int j = 0; j < 4; j++) acc[f][nf][j] = 0.f;

    // resolve chunk -> (A, Wh, Wl, K, kc)
    auto resolve = [&](int c, const float*& A, const __nv_bfloat16*& Wh,
                       const __nv_bfloat16*& Wl, int& K, int& kc) {
        if (c < nk0) { A = A0; Wh = W0h; Wl = W0l; K = K0; kc = c; }
        else         { A = A1; Wh = W1h; Wl = W1l; K = K1; kc = c - nk0; }
    };

    auto loadW = [&](int c, int buf) {
        const float* A; const __nv_bfloat16 *Wh, *Wl; int K, kc;
        resolve(c, A, Wh, Wl, K, kc);
        const uint32_t whb = sbase + buf * STAGE + 2 * BM * 128;
        const uint32_t wlb = whb + 8192;
        const __nv_bfloat16* WH = Wh + (size_t)n0 * K + kc * 64;
        const __nv_bfloat16* WL = Wl + (size_t)n0 * K + kc * 64;
        #pragma unroll
        for (int t = 0; t < 512 / T; t++) {
            int i = tid + t * T;
            int r = i >> 3, u = i & 7;
            uint32_t sw = SMEM_SWZ((uint32_t)(r * 128 + u * 16));
            cpa16(whb + sw, WH + (size_t)r * K + u * 8);
            cpa16(wlb + sw, WL + (size_t)r * K + u * 8);
        }
        asm volatile("cp.async.commit_group;" ::: "memory");
    };

    auto loadAregs = [&](int c, float4* v) {
        const float* A; const __nv_bfloat16 *Wh, *Wl; int K, kc;
        resolve(c, A, Wh, Wl, K, kc);
        const float* Ab = A + (size_t)m0 * K + kc * 64;
        #pragma unroll
        for (int t = 0; t < 8; t++) {
            int i = tid + t * T;
            int r = i >> 4, f = i & 15;
            v[t] = *(const float4*)(Ab + (size_t)r * K + f * 4);
        }
    };

    auto storeA = [&](const float4* v, int buf) {
        char* ab = dsm + buf * STAGE;
        #pragma unroll
        for (int t = 0; t < 8; t++) {
            int i = tid + t * T;
            int r = i >> 4, f = i & 15;
            uint32_t sw = SMEM_SWZ((uint32_t)(r * 128 + f * 8));
            __nv_bfloat16 hx = __float2bfloat16_rn(v[t].x);
            __nv_bfloat16 hy = __float2bfloat16_rn(v[t].y);
            __nv_bfloat16 hz = __float2bfloat16_rn(v[t].z);
            __nv_bfloat16 hw = __float2bfloat16_rn(v[t].w);
            *(__nv_bfloat162*)(ab + sw)     = __halves2bfloat162(hx, hy);
            *(__nv_bfloat162*)(ab + sw + 4) = __halves2bfloat162(hz, hw);
            __nv_bfloat16 lx = __float2bfloat16_rn(v[t].x - __bfloat162float(hx));
            __nv_bfloat16 ly = __float2bfloat16_rn(v[t].y - __bfloat162float(hy));
            __nv_bfloat16 lz = __float2bfloat16_rn(v[t].z - __bfloat162float(hz));
            __nv_bfloat16 lw = __float2bfloat16_rn(v[t].w - __bfloat162float(hw));
            *(__nv_bfloat162*)(ab + BM * 128 + sw)     = __halves2bfloat162(lx, ly);
            *(__nv_bfloat162*)(ab + BM * 128 + sw + 4) = __halves2bfloat162(lz, lw);
        }
    };

    // prologue: stage chunk 0 into buf 0
    loadW(0, 0);
    {
        float4 v[8];
        loadAregs(0, v);
        storeA(v, 0);
    }
    asm volatile("cp.async.wait_group 0;" ::: "memory");
    __syncthreads();

    #pragma unroll 1
    for (int it = 0; it < nItems; ++it) {
        const int cur = it & 1;
        const int nxt = cur ^ 1;
        const bool pre = (it + 1 < nItems);
        if (pre) loadW(it + 1, nxt);
        float4 v[8];
        if (pre) loadAregs(it + 1, v);

        // compute on cur
        const uint32_t aHi = sbase + cur * STAGE;
        const uint32_t aLo = aHi + BM * 128;
        const uint32_t bHi = sbase + cur * STAGE + 2 * BM * 128;
        const uint32_t bLo = bHi + 8192;
        #pragma unroll
        for (int ks = 0; ks < 4; ++ks) {
            uint32_t ahi[2][4], alo[2][4], bhi[2][4], blo[2][4];
            #pragma unroll
            for (int f = 0; f < 2; f++) {
                uint32_t off = (uint32_t)((warp_m * 32 + f * 16 + m_in) * 128 + ks * 32 + kb_a);
                LDSM4(ahi[f], aHi + SMEM_SWZ(off));
                LDSM4(alo[f], aLo + SMEM_SWZ(off));
            }
            #pragma unroll
            for (int g = 0; g < 2; g++) {
                uint32_t off = (uint32_t)((warp_n * 32 + g * 16 + n_in) * 128 + ks * 32 + kb_b);
                LDSM4(bhi[g], bHi + SMEM_SWZ(off));
                LDSM4(blo[g], bLo + SMEM_SWZ(off));
            }
            #pragma unroll
            for (int f = 0; f < 2; f++) {
                #pragma unroll
                for (int nf = 0; nf < 4; nf++) {
                    const int g = nf >> 1, j = (nf & 1) * 2;
                    MMA16816(acc[f][nf], ahi[f], bhi[g][j], bhi[g][j + 1]);
                    MMA16816(acc[f][nf], ahi[f], blo[g][j], blo[g][j + 1]);
                    MMA16816(acc[f][nf], alo[f], bhi[g][j], bhi[g][j + 1]);
                }
            }
        }

        if (pre) storeA(v, nxt);
        asm volatile("cp.async.wait_group 0;" ::: "memory");
        __syncthreads();
    }

    // epilogue
    const int rq = lane >> 2;
    const int cq = (lane & 3) * 2;
    #pragma unroll
    for (int f = 0; f < 2; f++) {
        #pragma unroll
        for (int nf = 0; nf < 4; nf++) {
            const int col = n0 + warp_n * 32 + nf * 8 + cq;
            const float bb0 = b1[col]     + (b2 ? b2[col]     : 0.f);
            const float bb1 = b1[col + 1] + (b2 ? b2[col + 1] : 0.f);
            const int row0 = m0 + warp_m * 32 + f * 16 + rq;
            float v0 = acc[f][nf][0] + bb0, v1 = acc[f][nf][1] + bb1;
            float v2 = acc[f][nf][2] + bb0, v3 = acc[f][nf][3] + bb1;
            if (ACT == 1) { v0 = tanhf(v0); v1 = tanhf(v1); v2 = tanhf(v2); v3 = tanhf(v3); }
            *(float2*)(C + (size_t)row0 * ldC + col)       = make_float2(v0, v1);
            *(float2*)(C + (size_t)(row0 + 8) * ldC + col) = make_float2(v2, v3);
        }
    }
}

// ---------------- weight split fp32 -> bf16 hi/lo ----------------
__global__ void __launch_bounds__(256)
wsplit_kernel(const float* __restrict__ w, __nv_bfloat16* __restrict__ hi,
              __nv_bfloat16* __restrict__ lo, int n4)
{
    int i = blockIdx.x * 256 + threadIdx.x;
    if (i >= n4) return;
    float4 v = ((const float4*)w)[i];
    __nv_bfloat16 hx = __float2bfloat16_rn(v.x);
    __nv_bfloat16 hy = __float2bfloat16_rn(v.y);
    __nv_bfloat16 hz = __float2bfloat16_rn(v.z);
    __nv_bfloat16 hw = __float2bfloat16_rn(v.w);
    *(__nv_bfloat162*)(hi + 4 * (size_t)i)     = __halves2bfloat162(hx, hy);
    *(__nv_bfloat162*)(hi + 4 * (size_t)i + 2) = __halves2bfloat162(hz, hw);
    __nv_bfloat16 lx = __float2bfloat16_rn(v.x - __bfloat162float(hx));
    __nv_bfloat16 ly = __float2bfloat16_rn(v.y - __bfloat162float(hy));
    __nv_bfloat16 lz = __float2bfloat16_rn(v.z - __bfloat162float(hz));
    __nv_bfloat16 lw = __float2bfloat16_rn(v.w - __bfloat162float(hw));
    *(__nv_bfloat162*)(lo + 4 * (size_t)i)     = __halves2bfloat162(lx, ly);
    *(__nv_bfloat162*)(lo + 4 * (size_t)i + 2) = __halves2bfloat162(lz, lw);
}

// ---------------- attention logits: warp per (b,n) row ----------------
__global__ void __launch_bounds__(256)
att_logits_kernel(const float* __restrict__ vea, const float* __restrict__ dec,
                  const float* __restrict__ faw, const float* __restrict__ fab,
                  float* __restrict__ logits)
{
    const int gw = blockIdx.x * 8 + (threadIdx.x >> 5);
    const int lane = threadIdx.x & 31;
    const int b = gw / Nn, n = gw % Nn;
    const float* row = vea + ((size_t)b * Nn + n) * ATT;
    const float* db = dec + b * ATT;
    const int a0 = lane * 8;
    float4 r0 = *(const float4*)(row + a0);
    float4 r1 = *(const float4*)(row + a0 + 4);
    float4 d0 = *(const float4*)(db + a0);
    float4 d1 = *(const float4*)(db + a0 + 4);
    float4 w0 = *(const float4*)(faw + a0);
    float4 w1 = *(const float4*)(faw + a0 + 4);
    float s = tanha(r0.x + d0.x) * w0.x + tanha(r0.y + d0.y) * w0.y
            + tanha(r0.z + d0.z) * w0.z + tanha(r0.w + d0.w) * w0.w
            + tanha(r1.x + d1.x) * w1.x + tanha(r1.y + d1.y) * w1.y
            + tanha(r1.z + d1.z) * w1.z + tanha(r1.w + d1.w) * w1.w;
    #pragma unroll
    for (int o = 16; o; o >>= 1) s += __shfl_xor_sync(0xffffffffu, s, o);
    if (lane == 0) logits[b * Nn + n] = s + fab[0];
}

// ---------------- softmax over N + att_out = scores @ vis_enc ----------------
__global__ void __launch_bounds__(256)
softmax_attout_kernel(const float* __restrict__ logits, const float* __restrict__ vis,
                      float* __restrict__ attout)
{
    const int b = blockIdx.x;
    const int slice = blockIdx.y;
    const int tx = threadIdx.x;
    __shared__ float sc[Nn];
    __shared__ float red[256];
    __shared__ float4 r4[256];

    float v = (tx < Nn) ? logits[b * Nn + tx] : -INFINITY;
    red[tx] = v;
    __syncthreads();
    #pragma unroll
    for (int o = 128; o; o >>= 1) {
        if (tx < o) red[tx] = fmaxf(red[tx], red[tx + o]);
        __syncthreads();
    }
    float mx = red[0];
    __syncthreads();
    float e = (tx < Nn) ? expf(v - mx) : 0.f;
    red[tx] = e;
    __syncthreads();
    #pragma unroll
    for (int o = 128; o; o >>= 1) {
        if (tx < o) red[tx] += red[tx + o];
        __syncthreads();
    }
    float inv = 1.f / red[0];
    if (tx < Nn) sc[tx] = e * inv;
    __syncthreads();

    const int cg = tx & 63;
    const int np = tx >> 6;
    const int d = slice * 256 + cg * 4;
    const float* base = vis + (size_t)b * Nn * Dd + d;
    float4 acc = make_float4(0.f, 0.f, 0.f, 0.f);
    #pragma unroll 7
    for (int n = np; n < Nn; n += 4) {
        float s = sc[n];
        float4 x = *(const float4*)(base + (size_t)n * Dd);
        acc.x = fmaf(s, x.x, acc.x);
        acc.y = fmaf(s, x.y, acc.y);
        acc.z = fmaf(s, x.z, acc.z);
        acc.w = fmaf(s, x.w, acc.w);
    }
    r4[tx] = acc;
    __syncthreads();
    if (np == 0) {
        float4 a1 = r4[tx + 64], a2 = r4[tx + 128], a3 = r4[tx + 192];
        acc.x += a1.x + a2.x + a3.x;
        acc.y += a1.y + a2.y + a3.y;
        acc.z += a1.z + a2.z + a3.z;
        acc.w += a1.w + a2.w + a3.w;
        *(float4*)(attout + (size_t)b * Dd + d) = acc;
    }
}

// ---------------- LSTM elementwise ----------------
__global__ void __launch_bounds__(256)
lstm_kernel(const float* __restrict__ gates, float* __restrict__ c, float* __restrict__ hnew)
{
    const int idx = blockIdx.x * 256 + threadIdx.x;
    const int b = idx / HID, hh = idx % HID;
    const float* gb = gates + (size_t)b * G4;
    float gi = gb[hh];
    float gf = gb[HID + hh];
    float gg = gb[2 * HID + hh];
    float go = gb[3 * HID + hh];
    float cn = sigmoidf_(gf) * c[idx] + sigmoidf_(gi) * tanhf(gg);
    c[idx] = cn;
    hnew[idx] = sigmoidf_(go) * tanhf(cn);
}

// ---------------- final stop head ----------------
__global__ void __launch_bounds__(256)
stop_final_kernel(const float* __restrict__ ppre, const float* __restrict__ fw,
                  const float* __restrict__ fb, float* __restrict__ outp, int s)
{
    const int b = blockIdx.x;
    const int tx = threadIdx.x;
    __shared__ float r0[256];
    __shared__ float r1[256];
    float v = ppre[b * ISD + tx];
    r0[tx] = v * fw[tx];
    r1[tx] = v * fw[ISD + tx];
    __syncthreads();
    #pragma unroll
    for (int o = 128; o; o >>= 1) {
        if (tx < o) { r0[tx] += r0[tx + o]; r1[tx] += r1[tx + o]; }
        __syncthreads();
    }
    if (tx == 0) {
        outp[(size_t)b * Ss * 2 + s * 2 + 0] = r0[0] + fb[0];
        outp[(size_t)b * Ss * 2 + s * 2 + 1] = r1[0] + fb[1];
    }
}

__global__ void zero2_kernel(float* __restrict__ a, float* __restrict__ b, int n)
{
    int i = blockIdx.x * 256 + threadIdx.x;
    if (i < n) { a[i] = 0.f; b[i] = 0.f; }
}

// ---------------- launch ----------------
extern "C" void kernel_launch(void* const* d_in, const int* in_sizes, int n_in,
                              void* d_out, int out_size)
{
    const float* vis        = (const float*)d_in[0];
    const float* enc_att_w  = (const float*)d_in[2];
    const float* enc_att_b  = (const float*)d_in[3];
    const float* dec_att_w  = (const float*)d_in[4];
    const float* dec_att_b  = (const float*)d_in[5];
    const float* full_att_w = (const float*)d_in[6];
    const float* full_att_b = (const float*)d_in[7];
    const float* ctx_w      = (const float*)d_in[8];
    const float* ctx_b      = (const float*)d_in[9];
    const float* W_ih       = (const float*)d_in[10];
    const float* b_ih       = (const float*)d_in[11];
    const float* W_hh       = (const float*)d_in[12];
    const float* b_hh       = (const float*)d_in[13];
    const float* topic_hid_w = (const float*)d_in[14];
    const float* topic_hid_b = (const float*)d_in[15];
    const float* topic_ctx_w = (const float*)d_in[16];
    const float* topic_ctx_b = (const float*)d_in[17];
    const float* stop_prev_w = (const float*)d_in[18];
    const float* stop_prev_b = (const float*)d_in[19];
    const float* stop_cur_w  = (const float*)d_in[20];
    const float* stop_cur_b  = (const float*)d_in[21];
    const float* final_stop_w = (const float*)d_in[22];
    const float* final_stop_b = (const float*)d_in[23];

    float* out = (float*)d_out;
    float* out_topics = out;
    float* out_ps     = out + (size_t)Bz * Ss * WID;

    float *vea, *hbase, *c, *dec, *logits, *attout, *ctx, *gates, *ppre;
    cudaGetSymbolAddress((void**)&vea,    g_vea);
    cudaGetSymbolAddress((void**)&hbase,  g_h);
    cudaGetSymbolAddress((void**)&c,      g_c);
    cudaGetSymbolAddress((void**)&dec,    g_dec);
    cudaGetSymbolAddress((void**)&logits, g_logits);
    cudaGetSymbolAddress((void**)&attout, g_attout);
    cudaGetSymbolAddress((void**)&ctx,    g_ctx);
    cudaGetSymbolAddress((void**)&gates,  g_gates);
    cudaGetSymbolAddress((void**)&ppre,   g_ppre);
    __nv_bfloat16 *wh, *wl;
    cudaGetSymbolAddress((void**)&wh, g_wh);
    cudaGetSymbolAddress((void**)&wl, g_wl);
    float* h0 = hbase;
    float* h1 = hbase + Bz * HID;

    constexpr int SM128 = 2 * (2 * 128 * 128 + 2 * 64 * 128);   // 98304
    constexpr int SM64  = 2 * (2 * 64 * 128 + 2 * 64 * 128);    // 65536
    cudaFuncSetAttribute(gemm_ms<128, 0>, cudaFuncAttributeMaxDynamicSharedMemorySize, SM128);
    cudaFuncSetAttribute(gemm_ms<128, 1>, cudaFuncAttributeMaxDynamicSharedMemorySize, SM128);
    cudaFuncSetAttribute(gemm_ms<64, 0>,  cudaFuncAttributeMaxDynamicSharedMemorySize, SM64);
    cudaFuncSetAttribute(gemm_ms<64, 1>,  cudaFuncAttributeMaxDynamicSharedMemorySize, SM64);

    // split weights
    {
        struct { const float* w; int off; int n; } ws[9] = {
            { enc_att_w,   OFF_ENC, ATT * Dd },
            { dec_att_w,   OFF_DEC, ATT * HID },
            { ctx_w,       OFF_CTX, SIN * Dd },
            { W_ih,        OFF_WIH, G4 * SIN },
            { W_hh,        OFF_WHH, G4 * HID },
            { topic_hid_w, OFF_TH,  WID * HID },
            { topic_ctx_w, OFF_TC,  WID * SIN },
            { stop_prev_w, OFF_SP,  ISD * HID },
            { stop_cur_w,  OFF_SC,  ISD * HID },
        };
        for (int i = 0; i < 9; i++) {
            int n4 = ws[i].n / 4;
            wsplit_kernel<<<(n4 + 255) / 256, 256>>>(ws[i].w, wh + ws[i].off, wl + ws[i].off, n4);
        }
    }

    zero2_kernel<<<(Bz * HID + 255) / 256, 256>>>(h0, c, Bz * HID);

    // precompute vis_enc_att : [B*N, ATT]
    gemm_ms<128, 0><<<dim3(ATT / 64, (Bz * Nn) / 128), 256, SM128>>>(
        vis, wh + OFF_ENC, wl + OFF_ENC, Dd,
        nullptr, nullptr, nullptr, 0,
        enc_att_b, nullptr, vea, ATT);

    for (int s = 0; s < Ss; s++) {
        float* hc = (s & 1) ? h1 : h0;
        float* hn = (s & 1) ? h0 : h1;

        gemm_ms<64, 0><<<dim3(ATT / 64, Bz / 64), 128, SM64>>>(
            hc, wh + OFF_DEC, wl + OFF_DEC, HID,
            nullptr, nullptr, nullptr, 0,
            dec_att_b, nullptr, dec, ATT);

        att_logits_kernel<<<(Bz * Nn) / 8, 256>>>(vea, dec, full_att_w, full_att_b, logits);

        softmax_attout_kernel<<<dim3(Bz, 4), 256>>>(logits, vis, attout);

        gemm_ms<128, 0><<<dim3(SIN / 64, Bz / 128), 256, SM128>>>(
            attout, wh + OFF_CTX, wl + OFF_CTX, Dd,
            nullptr, nullptr, nullptr, 0,
            ctx_b, nullptr, ctx, SIN);

        gemm_ms<128, 0><<<dim3(G4 / 64, Bz / 128), 256, SM128>>>(
            ctx, wh + OFF_WIH, wl + OFF_WIH, SIN,
            hc, wh + OFF_WHH, wl + OFF_WHH, HID,
            b_ih, b_hh, gates, G4);

        lstm_kernel<<<(Bz * HID) / 256, 256>>>(gates, c, hn);

        gemm_ms<128, 1><<<dim3(WID / 64, Bz / 128), 256, SM128>>>(
            hn, wh + OFF_TH, wl + OFF_TH, HID,
            ctx, wh + OFF_TC, wl + OFF_TC, SIN,
            topic_hid_b, topic_ctx_b, out_topics + (size_t)s * WID, Ss * WID);

        gemm_ms<64, 1><<<dim3(ISD / 64, Bz / 64), 128, SM64>>>(
            hc, wh + OFF_SP, wl + OFF_SP, HID,
            hn, wh + OFF_SC, wl + OFF_SC, HID,
            stop_prev_b, stop_cur_b, ppre, ISD);

        stop_final_kernel<<<Bz, 256>>>(ppre, final_stop_w, final_stop_b, out_ps, s);
    }
}